// round 6
// baseline (speedup 1.0000x reference)
#include <cuda_runtime.h>

// Volume rendering (NeRF-style) fused kernel — v3.
// Inputs: density (N,64,1) f32 in [0,1), depth_values (N,64) f32 sorted in [2,6],
// rays_feature (N,64,3) f32. Output buffer: feature (N,3) then depth (N).
//
// v3: each warp handles FOUR rays. 16-lane segments own one ray each, and each
// thread processes TWO rays (r and r+2) with all 10 float4 loads front-batched
// to double memory-level parallelism (MLP_p1 5 -> 10). Every LDG.128 remains
// perfectly coalesced (512 B contiguous per warp per load).
//
// cumprod(exp(-x)) == exp(-cumsum(x)) -> segmented (width-16) exclusive scan.
// fp32 detail: the 1e10 sentinel delta is excluded from the scan (its ulp would
// absorb the O(1) optical depth); it only feeds its own exp, which underflows
// to 0 exactly as in the reference.

#define N_PTS 64
#define FAR_DELTA 1e10f

struct RayIn {
    float4 dep, sig, fa, fb, fc;
};

__device__ __forceinline__ void render_ray(
    const RayIn& r, int sl, int n_rays, int ray, float* __restrict__ out)
{
    // depth[4*sl+4] lives in the next lane's dep.x (segment-local shfl)
    const float dnext = __shfl_down_sync(0xffffffffu, r.dep.x, 1, 16);

    const float sd0 = r.sig.x * (r.dep.y - r.dep.x);
    const float sd1 = r.sig.y * (r.dep.z - r.dep.y);
    const float sd2 = r.sig.z * (r.dep.w - r.dep.z);
    const float sd3 = r.sig.w * ((sl == 15) ? FAR_DELTA : (dnext - r.dep.w));

    // segmented exclusive prefix sum (sentinel excluded from the scan)
    const float local = sd0 + sd1 + sd2 + ((sl == 15) ? 0.0f : sd3);
    float scan = local;
    #pragma unroll
    for (int o = 1; o < 16; o <<= 1) {
        float v = __shfl_up_sync(0xffffffffu, scan, o, 16);
        if (sl >= o) scan += v;
    }
    const float excl = scan - local;

    const float T0 = __expf(-excl);
    const float e0 = __expf(-sd0);
    const float e1 = __expf(-sd1);
    const float e2 = __expf(-sd2);
    const float e3 = __expf(-sd3);            // underflows to 0 at sl==15
    const float w0 = T0 * (1.0f - e0);
    const float T1 = T0 * e0;
    const float w1 = T1 * (1.0f - e1);
    const float T2 = T1 * e1;
    const float w2 = T2 * (1.0f - e2);
    const float T3 = T2 * e2;
    const float w3 = T3 * (1.0f - e3);

    float fx = w0 * r.fa.x + w1 * r.fa.w + w2 * r.fb.z + w3 * r.fc.y;
    float fy = w0 * r.fa.y + w1 * r.fb.x + w2 * r.fb.w + w3 * r.fc.z;
    float fz = w0 * r.fa.z + w1 * r.fb.y + w2 * r.fc.x + w3 * r.fc.w;
    float dd = w0 * r.dep.x + w1 * r.dep.y + w2 * r.dep.z + w3 * r.dep.w;

    #pragma unroll
    for (int o = 8; o; o >>= 1) {
        fx += __shfl_xor_sync(0xffffffffu, fx, o, 16);
        fy += __shfl_xor_sync(0xffffffffu, fy, o, 16);
        fz += __shfl_xor_sync(0xffffffffu, fz, o, 16);
        dd += __shfl_xor_sync(0xffffffffu, dd, o, 16);
    }

    if (sl == 0) {
        out[(size_t)ray * 3 + 0] = fx;
        out[(size_t)ray * 3 + 1] = fy;
        out[(size_t)ray * 3 + 2] = fz;
        out[(size_t)n_rays * 3 + ray] = dd;
    }
}

__device__ __forceinline__ void load_ray(
    RayIn& r, const float* __restrict__ inA, const float* __restrict__ inB,
    const float* __restrict__ feat, int ray, int sl, float4& av, float4& bv)
{
    av = __ldcs(reinterpret_cast<const float4*>(inA + (size_t)ray * N_PTS) + sl);
    bv = __ldcs(reinterpret_cast<const float4*>(inB + (size_t)ray * N_PTS) + sl);
    const float4* f4 = reinterpret_cast<const float4*>(feat + (size_t)ray * (N_PTS * 3)) + sl * 3;
    r.fa = __ldcs(f4 + 0);
    r.fb = __ldcs(f4 + 1);
    r.fc = __ldcs(f4 + 2);
}

__global__ __launch_bounds__(256) void volrend_kernel(
    const float* __restrict__ inA,     // one of {density, depth}
    const float* __restrict__ inB,     // the other
    const float* __restrict__ feat,
    float* __restrict__ out,           // [0, 3N) feature, [3N, 4N) depth
    int n_rays)
{
    const int lane = threadIdx.x & 31;
    const int sl   = lane & 15;
    const int warp = threadIdx.x >> 5;
    const int wg   = blockIdx.x * (blockDim.x >> 5) + warp;
    const int ray0 = wg * 4 + (lane >> 4);
    const int ray1 = ray0 + 2;
    if (ray0 >= n_rays) return;
    const bool has1 = (ray1 < n_rays);

    // ---- front-batched loads: 10 independent LDG.128 per thread ----
    RayIn ra, rb;
    float4 av0, bv0, av1, bv1;
    load_ray(ra, inA, inB, feat, ray0, sl, av0, bv0);
    if (has1) load_ray(rb, inA, inB, feat, ray1, sl, av1, bv1);

    // Disambiguate density vs depth by value range (depth in [2,6]). Uniform.
    const bool a_is_depth = (av0.x >= 1.5f);
    ra.dep = a_is_depth ? av0 : bv0;
    ra.sig = a_is_depth ? bv0 : av0;

    render_ray(ra, sl, n_rays, ray0, out);

    if (has1) {
        rb.dep = a_is_depth ? av1 : bv1;
        rb.sig = a_is_depth ? bv1 : av1;
        render_ray(rb, sl, n_rays, ray1, out);
    }
}

extern "C" void kernel_launch(void* const* d_in, const int* in_sizes, int n_in,
                              void* d_out, int out_size)
{
    // Identify rays_feature by size: it is 3x larger than density/depth.
    int fi = 0;
    for (int i = 1; i < n_in; i++)
        if (in_sizes[i] > in_sizes[fi]) fi = i;
    const int ai = (fi == 0) ? 1 : 0;
    const int bi = 3 - fi - ai;

    const float* A    = (const float*)d_in[ai];
    const float* B    = (const float*)d_in[bi];
    const float* feat = (const float*)d_in[fi];
    float* out = (float*)d_out;

    const int n_rays = out_size / 4;          // out = feature(3N) + depth(N)

    const int threads = 256;                  // 8 warps = 32 rays per block
    const int rays_per_block = (threads / 32) * 4;
    const int blocks = (n_rays + rays_per_block - 1) / rays_per_block;
    volrend_kernel<<<blocks, threads>>>(A, B, feat, out, n_rays);
}